// round 2
// baseline (speedup 1.0000x reference)
#include <cuda_runtime.h>
#include <cstdint>

// Problem constants (fixed shapes for this problem instance; runtime sizes are
// still taken from in_sizes where it matters).
#define MAX_ENT   50000
#define MAX_E     1600000
#define MAX_REL   10       // N_REL - 1
#define C_DIM     128
#define C_VEC     (C_DIM / 4)   // 32 float4 per row

// ---------------- device scratch (static globals: no allocation allowed) ----
__device__ int      g_is64;
__device__ int      g_head[MAX_E];
__device__ unsigned g_val[MAX_E];          // packed tail | (rel<<20)
__device__ unsigned g_csr[MAX_E];          // CSR values: packed tail|rel
__device__ int      g_cnt[MAX_ENT];
__device__ int      g_row_start[MAX_ENT + 1];
__device__ int      g_fill[MAX_ENT];
__device__ float    g_embA[MAX_ENT * C_DIM];
__device__ float    g_embB[MAX_ENT * C_DIM];

// ---------------------------------------------------------------------------
// 0) zero per-head counters; block 0 / thread 0 also runs the int64/int32
//    width detection.  For int64 values < 2^31 (ids < 50000) every odd 32-bit
//    word is 0; for int32 random ids in [0,50000) 128 consecutive odd words
//    being all zero has probability ~(1/50000)^128 ~= 0.
__global__ void init_detect_kernel(const unsigned* __restrict__ words, int n_ent) {
    int i = blockIdx.x * blockDim.x + threadIdx.x;
    if (i < n_ent) g_cnt[i] = 0;
    if (i == 0) {
        int is64 = 1;
        #pragma unroll 1
        for (int k = 1; k < 256; k += 2) {
            if (words[k] != 0u) { is64 = 0; break; }
        }
        g_is64 = is64;
    }
}

// 1) decode edges into packed int32 form + histogram head degrees
__global__ void build_a_kernel(const void* __restrict__ edge_index,
                               const void* __restrict__ edge_type, int E) {
    int j = blockIdx.x * blockDim.x + threadIdx.x;
    if (j >= E) return;
    int head, tail, rel;
    if (g_is64) {
        const long long* ei = (const long long*)edge_index;
        const long long* et = (const long long*)edge_type;
        head = (int)ei[j];
        tail = (int)ei[E + j];
        rel  = (int)et[j] - 1;
    } else {
        const int* ei = (const int*)edge_index;
        const int* et = (const int*)edge_type;
        head = ei[j];
        tail = ei[E + j];
        rel  = et[j] - 1;
    }
    g_head[j] = head;
    g_val[j]  = (unsigned)tail | ((unsigned)rel << 20);
    atomicAdd(&g_cnt[head], 1);
}

// 2) exclusive scan of g_cnt -> g_row_start / g_fill.  Single block, 1024 thr.
__global__ void scan_kernel(int n_ent) {
    __shared__ int ssum[1024];
    const int t    = threadIdx.x;
    const int PER  = (n_ent + 1023) / 1024;
    const int base = t * PER;

    int s = 0;
    for (int i = 0; i < PER; i++) {
        int idx = base + i;
        if (idx < n_ent) s += g_cnt[idx];
    }
    ssum[t] = s;
    __syncthreads();
    // Hillis-Steele inclusive scan over the 1024 thread sums
    for (int off = 1; off < 1024; off <<= 1) {
        int v = (t >= off) ? ssum[t - off] : 0;
        __syncthreads();
        ssum[t] += v;
        __syncthreads();
    }
    int run = ssum[t] - s;   // exclusive prefix of this thread's chunk
    for (int i = 0; i < PER; i++) {
        int idx = base + i;
        if (idx < n_ent) {
            g_row_start[idx] = run;
            g_fill[idx]      = run;
            run += g_cnt[idx];
        }
    }
    if (t == 1023) g_row_start[n_ent] = ssum[1023];
}

// 3) fill CSR value array (slot order nondeterministic; affects fp-sum order
//    only, well inside the 1e-3 rel-err tolerance)
__global__ void build_b_kernel(int E) {
    int j = blockIdx.x * blockDim.x + threadIdx.x;
    if (j >= E) return;
    int head = g_head[j];
    int pos  = atomicAdd(&g_fill[head], 1);
    g_csr[pos] = g_val[j];
}

// 4) res = entity_emb   (output starts as the input embedding)
__global__ void init_res_kernel(const float4* __restrict__ emb,
                                float4* __restrict__ res, int n_vec) {
    int i = blockIdx.x * blockDim.x + threadIdx.x;
    if (i < n_vec) res[i] = emb[i];
}

// 5) one hop, fully fused: gather + relation scale + mean + L2-normalize +
//    ping-pong emb write + res accumulate.  One warp per entity.
//    mode: 0 -> src = entity_emb (input),  dst = g_embA
//          1 -> src = g_embA,              dst = g_embB
//          2 -> src = g_embB,              dst = g_embA
__global__ __launch_bounds__(256)
void hop_kernel(const float4* __restrict__ entity_emb,
                const float4* __restrict__ weight,
                float4* __restrict__ res,
                int n_ent, int n_rel, int mode) {
    __shared__ float4 sw[MAX_REL * C_VEC];   // 5 KB: all relation rows
    for (int i = threadIdx.x; i < n_rel * C_VEC; i += blockDim.x)
        sw[i] = weight[i];
    __syncthreads();

    const float4* src;
    float4* dst;
    if (mode == 0)      { src = entity_emb;            dst = (float4*)g_embA; }
    else if (mode == 1) { src = (const float4*)g_embA; dst = (float4*)g_embB; }
    else                { src = (const float4*)g_embB; dst = (float4*)g_embA; }

    int warp = (blockIdx.x * blockDim.x + threadIdx.x) >> 5;
    int lane = threadIdx.x & 31;
    if (warp >= n_ent) return;

    const int start = g_row_start[warp];
    const int end   = g_row_start[warp + 1];

    float4 acc = make_float4(0.f, 0.f, 0.f, 0.f);

    int k = start;
    // 4-wide unrolled mainloop: 4 independent 128-bit gathers in flight/lane
    for (; k + 3 < end; k += 4) {
        unsigned v0 = g_csr[k + 0];
        unsigned v1 = g_csr[k + 1];
        unsigned v2 = g_csr[k + 2];
        unsigned v3 = g_csr[k + 3];
        float4 x0 = src[(v0 & 0xFFFFFu) * C_VEC + lane];
        float4 x1 = src[(v1 & 0xFFFFFu) * C_VEC + lane];
        float4 x2 = src[(v2 & 0xFFFFFu) * C_VEC + lane];
        float4 x3 = src[(v3 & 0xFFFFFu) * C_VEC + lane];
        float4 w0 = sw[(v0 >> 20) * C_VEC + lane];
        float4 w1 = sw[(v1 >> 20) * C_VEC + lane];
        float4 w2 = sw[(v2 >> 20) * C_VEC + lane];
        float4 w3 = sw[(v3 >> 20) * C_VEC + lane];
        acc.x += x0.x * w0.x; acc.y += x0.y * w0.y; acc.z += x0.z * w0.z; acc.w += x0.w * w0.w;
        acc.x += x1.x * w1.x; acc.y += x1.y * w1.y; acc.z += x1.z * w1.z; acc.w += x1.w * w1.w;
        acc.x += x2.x * w2.x; acc.y += x2.y * w2.y; acc.z += x2.z * w2.z; acc.w += x2.w * w2.w;
        acc.x += x3.x * w3.x; acc.y += x3.y * w3.y; acc.z += x3.z * w3.z; acc.w += x3.w * w3.w;
    }
    for (; k < end; k++) {
        unsigned v = g_csr[k];
        float4 x = src[(v & 0xFFFFFu) * C_VEC + lane];
        float4 w = sw[(v >> 20) * C_VEC + lane];
        acc.x += x.x * w.x; acc.y += x.y * w.y; acc.z += x.z * w.z; acc.w += x.w * w.w;
    }

    // scatter_mean: divide by max(in-degree, 1)
    float deg = (float)(end - start);
    float inv = 1.0f / fmaxf(deg, 1.0f);
    acc.x *= inv; acc.y *= inv; acc.z *= inv; acc.w *= inv;

    // L2 norm across the 128 channels (4 per lane, 32 lanes)
    float ss = acc.x * acc.x + acc.y * acc.y + acc.z * acc.z + acc.w * acc.w;
    #pragma unroll
    for (int off = 16; off > 0; off >>= 1)
        ss += __shfl_xor_sync(0xFFFFFFFFu, ss, off);
    float nrm   = sqrtf(ss);
    float scale = 1.0f / fmaxf(nrm, 1e-12f);

    float4 o = make_float4(acc.x * scale, acc.y * scale, acc.z * scale, acc.w * scale);

    int idx = warp * C_VEC + lane;
    dst[idx] = o;
    float4 r = res[idx];
    r.x += o.x; r.y += o.y; r.z += o.z; r.w += o.w;
    res[idx] = r;
}

// ---------------------------------------------------------------------------
extern "C" void kernel_launch(void* const* d_in, const int* in_sizes, int n_in,
                              void* d_out, int out_size) {
    const float*  entity_emb = (const float*)d_in[0];
    const void*   edge_index = d_in[1];
    const void*   edge_type  = d_in[2];
    const float*  weight     = (const float*)d_in[3];

    const int n_ent = in_sizes[0] / C_DIM;     // 50000
    const int E     = in_sizes[2];             // 1600000
    const int n_rel = in_sizes[3] / C_DIM;     // 10

    const int TB = 256;

    // CSR build (once per launch; reused across the 3 hops)
    init_detect_kernel<<<(n_ent + TB - 1) / TB, TB>>>((const unsigned*)edge_index, n_ent);
    build_a_kernel<<<(E + TB - 1) / TB, TB>>>(edge_index, edge_type, E);
    scan_kernel<<<1, 1024>>>(n_ent);
    build_b_kernel<<<(E + TB - 1) / TB, TB>>>(E);

    // res = entity_emb
    const int n_vec = n_ent * C_VEC;
    init_res_kernel<<<(n_vec + TB - 1) / TB, TB>>>(
        (const float4*)entity_emb, (float4*)d_out, n_vec);

    // 3 hops, one warp per entity (8 warps/block)
    const int hop_blocks = (n_ent * 32 + TB - 1) / TB;
    hop_kernel<<<hop_blocks, TB>>>((const float4*)entity_emb,
                                   (const float4*)weight,
                                   (float4*)d_out, n_ent, n_rel, 0);
    hop_kernel<<<hop_blocks, TB>>>((const float4*)entity_emb,
                                   (const float4*)weight,
                                   (float4*)d_out, n_ent, n_rel, 1);
    hop_kernel<<<hop_blocks, TB>>>((const float4*)entity_emb,
                                   (const float4*)weight,
                                   (float4*)d_out, n_ent, n_rel, 2);
}

// round 3
// speedup vs baseline: 1.3456x; 1.3456x over previous
#include <cuda_runtime.h>
#include <cuda_fp16.h>
#include <cstdint>

#define MAX_ENT   50000
#define MAX_E     1600000
#define MAX_REL   10       // N_REL - 1
#define C_DIM     128
#define C_VEC     (C_DIM / 4)    // 32 float4 per row
#define C_H2V     (C_DIM / 4)    // 32 uint2 (4 halves) per row

// ---------------- device scratch (static globals: no allocation allowed) ----
__device__ int            g_is64;
__device__ int            g_head[MAX_E];
__device__ unsigned short g_rank[MAX_E];     // within-head slot from histogram
__device__ unsigned       g_val[MAX_E];      // packed tail | (rel<<20)
__device__ unsigned       g_csr[MAX_E];      // CSR values: packed tail|rel
__device__ int            g_cnt[MAX_ENT];
__device__ int            g_row_start[MAX_ENT + 1];
__device__ uint2          g_embH[MAX_ENT * C_H2V];  // fp16 input embeddings
__device__ uint2          g_embA[MAX_ENT * C_H2V];  // fp16 ping
__device__ uint2          g_embB[MAX_ENT * C_H2V];  // fp16 pong

// ---------------------------------------------------------------------------
// 0) zero per-head counters + int64/int32 width detection (see R1 notes:
//    int64 ids < 2^31 have all odd 32-bit words zero; impossible for the
//    int32 interpretation of random ids in [0,50000)).
__global__ void init_detect_kernel(const unsigned* __restrict__ words, int n_ent) {
    int i = blockIdx.x * blockDim.x + threadIdx.x;
    if (i < n_ent) g_cnt[i] = 0;
    if (i == 0) {
        int is64 = 1;
        #pragma unroll 1
        for (int k = 1; k < 256; k += 2) {
            if (words[k] != 0u) { is64 = 0; break; }
        }
        g_is64 = is64;
    }
}

// 1) decode edges, histogram head degrees, record within-head rank
__global__ void build_a_kernel(const void* __restrict__ edge_index,
                               const void* __restrict__ edge_type, int E) {
    int j = blockIdx.x * blockDim.x + threadIdx.x;
    if (j >= E) return;
    int head, tail, rel;
    if (g_is64) {
        const long long* ei = (const long long*)edge_index;
        const long long* et = (const long long*)edge_type;
        head = (int)ei[j];
        tail = (int)ei[E + j];
        rel  = (int)et[j] - 1;
    } else {
        const int* ei = (const int*)edge_index;
        const int* et = (const int*)edge_type;
        head = ei[j];
        tail = ei[E + j];
        rel  = et[j] - 1;
    }
    g_head[j] = head;
    g_val[j]  = (unsigned)tail | ((unsigned)rel << 20);
    int r = atomicAdd(&g_cnt[head], 1);
    g_rank[j] = (unsigned short)r;           // degrees ~Poisson(32) << 65536
}

// 2) exclusive scan of g_cnt -> g_row_start.  Single block, 1024 threads.
__global__ void scan_kernel(int n_ent) {
    __shared__ int ssum[1024];
    const int t    = threadIdx.x;
    const int PER  = (n_ent + 1023) / 1024;
    const int base = t * PER;

    int s = 0;
    for (int i = 0; i < PER; i++) {
        int idx = base + i;
        if (idx < n_ent) s += g_cnt[idx];
    }
    ssum[t] = s;
    __syncthreads();
    for (int off = 1; off < 1024; off <<= 1) {
        int v = (t >= off) ? ssum[t - off] : 0;
        __syncthreads();
        ssum[t] += v;
        __syncthreads();
    }
    int run = ssum[t] - s;
    for (int i = 0; i < PER; i++) {
        int idx = base + i;
        if (idx < n_ent) {
            g_row_start[idx] = run;
            run += g_cnt[idx];
        }
    }
    if (t == 1023) g_row_start[n_ent] = ssum[1023];
}

// 3) fill CSR values -- atomic-free: pos = row_start[head] + rank
__global__ void build_b_kernel(int E) {
    int j = blockIdx.x * blockDim.x + threadIdx.x;
    if (j >= E) return;
    int pos = g_row_start[g_head[j]] + (int)g_rank[j];
    g_csr[pos] = g_val[j];
}

// 4) convert entity_emb (fp32) -> fp16 table g_embH
__global__ void convert_kernel(const float4* __restrict__ emb, int n_vec) {
    int i = blockIdx.x * blockDim.x + threadIdx.x;
    if (i >= n_vec) return;
    float4 f = emb[i];
    __half2 a = __floats2half2_rn(f.x, f.y);
    __half2 b = __floats2half2_rn(f.z, f.w);
    uint2 q;
    q.x = *(unsigned*)&a;
    q.y = *(unsigned*)&b;
    g_embH[i] = q;
}

// 5) fused hop: fp16 gather + relation scale + mean + L2-normalize +
//    fp16 ping-pong write + fp32 res accumulate.  One warp per entity.
//    hop==0 additionally initializes res = entity_emb + o.
__global__ __launch_bounds__(256)
void hop_kernel(const float4* __restrict__ entity_emb,
                const float4* __restrict__ weight,
                float4* __restrict__ res,
                int n_ent, int n_rel, int hop) {
    __shared__ float4 sw[MAX_REL * C_VEC];   // 5 KB: all relation rows fp32
    for (int i = threadIdx.x; i < n_rel * C_VEC; i += blockDim.x)
        sw[i] = weight[i];
    __syncthreads();

    const uint2* src;
    uint2* dst;
    if (hop == 0)      { src = (const uint2*)g_embH; dst = (uint2*)g_embA; }
    else if (hop == 1) { src = (const uint2*)g_embA; dst = (uint2*)g_embB; }
    else               { src = (const uint2*)g_embB; dst = (uint2*)g_embA; }

    int warp = (blockIdx.x * blockDim.x + threadIdx.x) >> 5;
    int lane = threadIdx.x & 31;
    if (warp >= n_ent) return;

    const int start = g_row_start[warp];
    const int end   = g_row_start[warp + 1];

    float4 acc = make_float4(0.f, 0.f, 0.f, 0.f);

    int k = start;
    // 8-wide unroll: 8 independent 64-bit gathers in flight per lane
    for (; k + 7 < end; k += 8) {
        unsigned v[8];
        uint2 p[8];
        #pragma unroll
        for (int u = 0; u < 8; u++) v[u] = g_csr[k + u];
        #pragma unroll
        for (int u = 0; u < 8; u++)
            p[u] = src[(v[u] & 0xFFFFFu) * C_H2V + lane];
        #pragma unroll
        for (int u = 0; u < 8; u++) {
            float4 w = sw[(v[u] >> 20) * C_VEC + lane];
            float2 fa = __half22float2(*(__half2*)&p[u].x);
            float2 fb = __half22float2(*(__half2*)&p[u].y);
            acc.x += fa.x * w.x; acc.y += fa.y * w.y;
            acc.z += fb.x * w.z; acc.w += fb.y * w.w;
        }
    }
    for (; k < end; k++) {
        unsigned v = g_csr[k];
        uint2 p = src[(v & 0xFFFFFu) * C_H2V + lane];
        float4 w = sw[(v >> 20) * C_VEC + lane];
        float2 fa = __half22float2(*(__half2*)&p.x);
        float2 fb = __half22float2(*(__half2*)&p.y);
        acc.x += fa.x * w.x; acc.y += fa.y * w.y;
        acc.z += fb.x * w.z; acc.w += fb.y * w.w;
    }

    // scatter_mean
    float deg = (float)(end - start);
    float inv = 1.0f / fmaxf(deg, 1.0f);
    acc.x *= inv; acc.y *= inv; acc.z *= inv; acc.w *= inv;

    // L2 norm across 128 channels
    float ss = acc.x * acc.x + acc.y * acc.y + acc.z * acc.z + acc.w * acc.w;
    #pragma unroll
    for (int off = 16; off > 0; off >>= 1)
        ss += __shfl_xor_sync(0xFFFFFFFFu, ss, off);
    float scale = 1.0f / fmaxf(sqrtf(ss), 1e-12f);

    float4 o = make_float4(acc.x * scale, acc.y * scale,
                           acc.z * scale, acc.w * scale);

    int idx = warp * C_VEC + lane;

    // fp16 ping-pong write for the next hop's gather
    __half2 ha = __floats2half2_rn(o.x, o.y);
    __half2 hb = __floats2half2_rn(o.z, o.w);
    uint2 q;
    q.x = *(unsigned*)&ha;
    q.y = *(unsigned*)&hb;
    dst[idx] = q;

    // fp32 result accumulation (hop 0 fuses the res = entity_emb init)
    float4 r = (hop == 0) ? entity_emb[idx] : res[idx];
    r.x += o.x; r.y += o.y; r.z += o.z; r.w += o.w;
    res[idx] = r;
}

// ---------------------------------------------------------------------------
extern "C" void kernel_launch(void* const* d_in, const int* in_sizes, int n_in,
                              void* d_out, int out_size) {
    const float*  entity_emb = (const float*)d_in[0];
    const void*   edge_index = d_in[1];
    const void*   edge_type  = d_in[2];
    const float*  weight     = (const float*)d_in[3];

    const int n_ent = in_sizes[0] / C_DIM;     // 50000
    const int E     = in_sizes[2];             // 1600000
    const int n_rel = in_sizes[3] / C_DIM;     // 10

    const int TB = 256;
    const int n_vec = n_ent * C_VEC;

    // CSR build (once per launch; reused across the 3 hops)
    init_detect_kernel<<<(n_ent + TB - 1) / TB, TB>>>((const unsigned*)edge_index, n_ent);
    build_a_kernel<<<(E + TB - 1) / TB, TB>>>(edge_index, edge_type, E);
    scan_kernel<<<1, 1024>>>(n_ent);
    build_b_kernel<<<(E + TB - 1) / TB, TB>>>(E);
    convert_kernel<<<(n_vec + TB - 1) / TB, TB>>>((const float4*)entity_emb, n_vec);

    // 3 fused hops, one warp per entity (8 warps/block)
    const int hop_blocks = (n_ent * 32 + TB - 1) / TB;
    hop_kernel<<<hop_blocks, TB>>>((const float4*)entity_emb,
                                   (const float4*)weight,
                                   (float4*)d_out, n_ent, n_rel, 0);
    hop_kernel<<<hop_blocks, TB>>>((const float4*)entity_emb,
                                   (const float4*)weight,
                                   (float4*)d_out, n_ent, n_rel, 1);
    hop_kernel<<<hop_blocks, TB>>>((const float4*)entity_emb,
                                   (const float4*)weight,
                                   (float4*)d_out, n_ent, n_rel, 2);
}